// round 1
// baseline (speedup 1.0000x reference)
#include <cuda_runtime.h>

#define NN 50000
#define NE 800000
#define H  64
#define REL 5

// ---- device scratch (static globals; no runtime allocation) ----
__device__ float g_z[NN * H];            // x * dis[col]  (12.8 MB)
__device__ float g_y[REL * NN * H];      // y_r = x @ W_rel[r]  (64 MB)
__device__ float g_gcn[NN * H];          // sum z[c] over edges into row
__device__ float g_ssum[NN * H];         // sum exp(res)
__device__ float g_num[NN * H];          // sum res*exp(res)
__device__ int   g_deg[NN];
__device__ float g_WC[6 * H * H];        // [W_in | W_in@W_rel_r]
__device__ float g_BC[6 * H];            // [b    | b@W_rel_r]

__device__ __forceinline__ void red_add_v4(float* a, float4 v) {
    asm volatile("red.global.add.v4.f32 [%0], {%1,%2,%3,%4};"
                 :: "l"(a), "f"(v.x), "f"(v.y), "f"(v.z), "f"(v.w)
                 : "memory");
}

__global__ void k_zero() {
    int i = blockIdx.x * blockDim.x + threadIdx.x;
    int stride = gridDim.x * blockDim.x;
    float4 z4 = make_float4(0.f, 0.f, 0.f, 0.f);
    for (int j = i; j < NN * (H / 4); j += stride) {
        ((float4*)g_gcn)[j]  = z4;
        ((float4*)g_ssum)[j] = z4;
        ((float4*)g_num)[j]  = z4;
    }
    for (int j = i; j < NN; j += stride) g_deg[j] = 0;
}

// Combined weights: WC[0]=W_in, BC[0]=b_in; WC[1+r]=W_in@W_rel[r], BC[1+r]=b@W_rel[r]
__global__ void k_wcomb(const float* __restrict__ Win, const float* __restrict__ bin,
                        const float* __restrict__ Wrel) {
    int idx = blockIdx.x * blockDim.x + threadIdx.x;
    if (idx >= 6 * H * H) return;
    int m = idx >> 12, k = (idx >> 6) & 63, h = idx & 63;
    if (m == 0) {
        g_WC[idx] = Win[k * H + h];
        if (k == 0) g_BC[h] = bin[h];
    } else {
        const float* Wr = Wrel + (m - 1) * H * H;
        float s = 0.f;
        #pragma unroll 8
        for (int j = 0; j < H; j++) s += Win[k * H + j] * Wr[j * H + h];
        g_WC[idx] = s;
        if (k == 0) {
            float sb = 0.f;
            for (int j = 0; j < H; j++) sb += bin[j] * Wr[j * H + h];
            g_BC[m * H + h] = sb;
        }
    }
}

__global__ void k_deg(const int* __restrict__ ei) {
    int e = blockIdx.x * blockDim.x + threadIdx.x;
    if (e < NE) atomicAdd(&g_deg[ei[NE + e]], 1);
}

// Node GEMM: per block 16 nodes; thread (ty=node, tx=float4 channel group).
// Computes x (-> z = x*dis) and the 5 y_r planes from risk via combined weights.
__global__ void k_node(const float* __restrict__ risk) {
    __shared__ float sA[16 * H];
    __shared__ float sW[H * H];
    __shared__ float sB[H];
    int t = threadIdx.x;
    int ty = t >> 4, tx = t & 15;
    int node0 = blockIdx.x * 16;

    ((float4*)sA)[t] = ((const float4*)(risk + node0 * H))[t];
    int dg = g_deg[node0 + ty];
    float dis = dg > 0 ? rsqrtf((float)dg) : 0.f;

    for (int m = 0; m < 6; m++) {
        __syncthreads();
        #pragma unroll
        for (int i = 0; i < 4; i++)
            ((float4*)sW)[t + 256 * i] = ((const float4*)(g_WC + m * H * H))[t + 256 * i];
        if (t < H) sB[t] = g_BC[m * H + t];
        __syncthreads();

        float4 acc = ((float4*)sB)[tx];
        #pragma unroll
        for (int k = 0; k < H; k++) {
            float a = sA[ty * H + k];
            float4 w = ((float4*)sW)[k * 16 + tx];
            acc.x += a * w.x; acc.y += a * w.y; acc.z += a * w.z; acc.w += a * w.w;
        }
        int n = node0 + ty;
        if (m == 0) {
            float4 zz = make_float4(acc.x * dis, acc.y * dis, acc.z * dis, acc.w * dis);
            ((float4*)g_z)[n * 16 + tx] = zz;
        } else {
            ((float4*)g_y)[((m - 1) * NN + n) * 16 + tx] = acc;
        }
    }
}

// Single edge pass: half-warp (16 lanes x float4) per edge.
// Accumulates gcn (z[c]), ssum (exp(res)), num (res*exp(res)) into dst row.
__global__ void k_edge(const int* __restrict__ ei, const int* __restrict__ et) {
    int t = threadIdx.x;
    int e = blockIdx.x * 16 + (t >> 4);
    int l = t & 15;
    int r  = ei[e];
    int c  = ei[NE + e];
    int tp = et[e];

    float4 zv = ((const float4*)g_z)[c * 16 + l];
    float4 yv = ((const float4*)g_y)[(tp * NN + c) * 16 + l];
    float4 ev = make_float4(__expf(yv.x), __expf(yv.y), __expf(yv.z), __expf(yv.w));
    float4 nv = make_float4(yv.x * ev.x, yv.y * ev.y, yv.z * ev.z, yv.w * ev.w);

    int o = r * H + l * 4;
    red_add_v4(g_gcn  + o, zv);
    red_add_v4(g_ssum + o, ev);
    red_add_v4(g_num  + o, nv);
}

// Output: m = dis[n]*gcn + 0.5*relu(num/(ssum+1e-16)); out = m @ W_out + b_out
__global__ void k_out(const float* __restrict__ Wout, const float* __restrict__ bout,
                      float* __restrict__ out) {
    __shared__ float sM[16 * H];
    __shared__ float sW[H * H];
    __shared__ float sB[H];
    int t = threadIdx.x, ty = t >> 4, tx = t & 15;
    int n = blockIdx.x * 16 + ty;

    int dg = g_deg[n];
    float dis = dg > 0 ? rsqrtf((float)dg) : 0.f;
    float4 g = ((float4*)g_gcn)[n * 16 + tx];
    float4 s = ((float4*)g_ssum)[n * 16 + tx];
    float4 u = ((float4*)g_num)[n * 16 + tx];
    float4 mm;
    mm.x = dis * g.x + 0.5f * fmaxf(u.x / (s.x + 1e-16f), 0.f);
    mm.y = dis * g.y + 0.5f * fmaxf(u.y / (s.y + 1e-16f), 0.f);
    mm.z = dis * g.z + 0.5f * fmaxf(u.z / (s.z + 1e-16f), 0.f);
    mm.w = dis * g.w + 0.5f * fmaxf(u.w / (s.w + 1e-16f), 0.f);
    ((float4*)sM)[ty * 16 + tx] = mm;

    #pragma unroll
    for (int i = 0; i < 4; i++)
        ((float4*)sW)[t + 256 * i] = ((const float4*)Wout)[t + 256 * i];
    if (t < H) sB[t] = bout[t];
    __syncthreads();

    float4 acc = ((float4*)sB)[tx];
    #pragma unroll
    for (int k = 0; k < H; k++) {
        float a = sM[ty * H + k];
        float4 w = ((float4*)sW)[k * 16 + tx];
        acc.x += a * w.x; acc.y += a * w.y; acc.z += a * w.z; acc.w += a * w.w;
    }
    ((float4*)out)[n * 16 + tx] = acc;
}

extern "C" void kernel_launch(void* const* d_in, const int* in_sizes, int n_in,
                              void* d_out, int out_size) {
    const float* risk = (const float*)d_in[0];
    // d_in[1] = edge_weight (unused by the reference)
    const float* Win  = (const float*)d_in[2];
    const float* bin  = (const float*)d_in[3];
    const float* Wrel = (const float*)d_in[4];
    const float* Wout = (const float*)d_in[5];
    const float* bout = (const float*)d_in[6];
    const int*   ei   = (const int*)d_in[7];   // [2, NE]: row (dst), col (src)
    const int*   et   = (const int*)d_in[8];
    float* out = (float*)d_out;

    k_zero<<<512, 256>>>();
    k_wcomb<<<(6 * H * H + 255) / 256, 256>>>(Win, bin, Wrel);
    k_deg<<<(NE + 255) / 256, 256>>>(ei);
    k_node<<<NN / 16, 256>>>(risk);
    k_edge<<<NE / 16, 256>>>(ei, et);
    k_out<<<NN / 16, 256>>>(Wout, bout, out);
}

// round 2
// speedup vs baseline: 1.4922x; 1.4922x over previous
#include <cuda_runtime.h>

#define NN 50000
#define NE 800000
#define H  64
#define REL 5

// ---- device scratch (static globals; no runtime allocation) ----
__device__ float g_z[NN * H];            // x * dis[col]  (12.8 MB)
__device__ float g_y[REL * NN * H];      // y_r = x @ W_rel[r]  (64 MB)
__device__ float g_gcn[NN * H];          // sum z[c] over edges into row
__device__ float g_ssum[NN * H];         // sum exp(res)
__device__ float g_num[NN * H];          // sum res*exp(res)
__device__ int   g_deg[NN];
__device__ float g_WC[6 * H * H];        // [W_in | W_in@W_rel_r]
__device__ float g_BC[6 * H];            // [b    | b@W_rel_r]

__device__ __forceinline__ void red_add_v4(float* a, float4 v) {
    asm volatile("red.global.add.v4.f32 [%0], {%1,%2,%3,%4};"
                 :: "l"(a), "f"(v.x), "f"(v.y), "f"(v.z), "f"(v.w)
                 : "memory");
}

__global__ void k_zero() {
    int i = blockIdx.x * blockDim.x + threadIdx.x;
    int stride = gridDim.x * blockDim.x;
    float4 z4 = make_float4(0.f, 0.f, 0.f, 0.f);
    for (int j = i; j < NN * (H / 4); j += stride) {
        ((float4*)g_gcn)[j]  = z4;
        ((float4*)g_ssum)[j] = z4;
        ((float4*)g_num)[j]  = z4;
    }
    for (int j = i; j < NN; j += stride) g_deg[j] = 0;
}

// Combined weights: WC[0]=W_in, BC[0]=b_in; WC[1+r]=W_in@W_rel[r], BC[1+r]=b@W_rel[r]
__global__ void k_wcomb(const float* __restrict__ Win, const float* __restrict__ bin,
                        const float* __restrict__ Wrel) {
    int idx = blockIdx.x * blockDim.x + threadIdx.x;
    if (idx >= 6 * H * H) return;
    int m = idx >> 12, k = (idx >> 6) & 63, h = idx & 63;
    if (m == 0) {
        g_WC[idx] = Win[k * H + h];
        if (k == 0) g_BC[h] = bin[h];
    } else {
        const float* Wr = Wrel + (m - 1) * H * H;
        float s = 0.f;
        #pragma unroll 8
        for (int j = 0; j < H; j++) s += Win[k * H + j] * Wr[j * H + h];
        g_WC[idx] = s;
        if (k == 0) {
            float sb = 0.f;
            for (int j = 0; j < H; j++) sb += bin[j] * Wr[j * H + h];
            g_BC[m * H + h] = sb;
        }
    }
}

__global__ void k_deg(const int* __restrict__ ei) {
    int e = blockIdx.x * blockDim.x + threadIdx.x;
    if (e < NE) atomicAdd(&g_deg[ei[NE + e]], 1);
}

#define SA_STRIDE 68   // floats; multiple of 4 (16B alignment), 68 mod 32 = 4 banks

// Node GEMM v2: block tile 64 nodes x 64 cols, thread micro-tile 4x4.
// sAT[k][node] transposed so the inner loop is 2x LDS.128 -> 16 FMA.
__global__ void __launch_bounds__(256) k_node(const float* __restrict__ risk) {
    __shared__ float sAT[H * SA_STRIDE];
    __shared__ float sW[H * H];
    __shared__ float sB[H];
    int t = threadIdx.x;
    int node0 = blockIdx.x * 64;

    // Load + transpose A tile (guarded: last block is partial)
    for (int i = t; i < 64 * 16; i += 256) {
        int nd = i >> 4, kg = i & 15;
        float4 a = make_float4(0.f, 0.f, 0.f, 0.f);
        if (node0 + nd < NN) a = ((const float4*)risk)[(node0 + nd) * 16 + kg];
        sAT[(kg * 4 + 0) * SA_STRIDE + nd] = a.x;
        sAT[(kg * 4 + 1) * SA_STRIDE + nd] = a.y;
        sAT[(kg * 4 + 2) * SA_STRIDE + nd] = a.z;
        sAT[(kg * 4 + 3) * SA_STRIDE + nd] = a.w;
    }

    int rg = t >> 4;   // node group: 16 groups x 4 nodes
    int cg = t & 15;   // col group : 16 groups x 4 cols

    for (int m = 0; m < 6; m++) {
        __syncthreads();
        #pragma unroll
        for (int i = 0; i < 4; i++)
            ((float4*)sW)[t + 256 * i] = ((const float4*)(g_WC + m * H * H))[t + 256 * i];
        if (t < H) sB[t] = g_BC[m * H + t];
        __syncthreads();

        float4 b = ((float4*)sB)[cg];
        float4 acc[4];
        #pragma unroll
        for (int j = 0; j < 4; j++) acc[j] = b;

        #pragma unroll 16
        for (int k = 0; k < H; k++) {
            float4 av = *(const float4*)&sAT[k * SA_STRIDE + rg * 4];
            float4 w  = ((const float4*)sW)[k * 16 + cg];
            acc[0].x += av.x * w.x; acc[0].y += av.x * w.y; acc[0].z += av.x * w.z; acc[0].w += av.x * w.w;
            acc[1].x += av.y * w.x; acc[1].y += av.y * w.y; acc[1].z += av.y * w.z; acc[1].w += av.y * w.w;
            acc[2].x += av.z * w.x; acc[2].y += av.z * w.y; acc[2].z += av.z * w.z; acc[2].w += av.z * w.w;
            acc[3].x += av.w * w.x; acc[3].y += av.w * w.y; acc[3].z += av.w * w.z; acc[3].w += av.w * w.w;
        }

        int nbase = node0 + rg * 4;
        if (m == 0) {
            #pragma unroll
            for (int j = 0; j < 4; j++) {
                int n = nbase + j;
                if (n < NN) {
                    int dg = g_deg[n];
                    float dis = dg > 0 ? rsqrtf((float)dg) : 0.f;
                    float4 zz = make_float4(acc[j].x * dis, acc[j].y * dis,
                                            acc[j].z * dis, acc[j].w * dis);
                    ((float4*)g_z)[n * 16 + cg] = zz;
                }
            }
        } else {
            #pragma unroll
            for (int j = 0; j < 4; j++) {
                int n = nbase + j;
                if (n < NN)
                    ((float4*)g_y)[((m - 1) * NN + n) * 16 + cg] = acc[j];
            }
        }
    }
}

// Single edge pass: half-warp (16 lanes x float4) per edge.
// Accumulates gcn (z[c]), ssum (exp(res)), num (res*exp(res)) into dst row.
__global__ void k_edge(const int* __restrict__ ei, const int* __restrict__ et) {
    int t = threadIdx.x;
    int e = blockIdx.x * 16 + (t >> 4);
    int l = t & 15;
    int r  = ei[e];
    int c  = ei[NE + e];
    int tp = et[e];

    float4 zv = ((const float4*)g_z)[c * 16 + l];
    float4 yv = ((const float4*)g_y)[(tp * NN + c) * 16 + l];
    float4 ev = make_float4(__expf(yv.x), __expf(yv.y), __expf(yv.z), __expf(yv.w));
    float4 nv = make_float4(yv.x * ev.x, yv.y * ev.y, yv.z * ev.z, yv.w * ev.w);

    int o = r * H + l * 4;
    red_add_v4(g_gcn  + o, zv);
    red_add_v4(g_ssum + o, ev);
    red_add_v4(g_num  + o, nv);
}

// Output: m = dis[n]*gcn + 0.5*relu(num/(ssum+1e-16)); out = m @ W_out + b_out
// Same 64x64 block tile / 4x4 micro-tile structure as k_node.
__global__ void __launch_bounds__(256) k_out(const float* __restrict__ Wout,
                                             const float* __restrict__ bout,
                                             float* __restrict__ out) {
    __shared__ float sMT[H * SA_STRIDE];
    __shared__ float sW[H * H];
    __shared__ float sB[H];
    int t = threadIdx.x;
    int node0 = blockIdx.x * 64;

    // Epilogue + transpose into shared
    for (int i = t; i < 64 * 16; i += 256) {
        int nd = i >> 4, kg = i & 15;
        float4 mm = make_float4(0.f, 0.f, 0.f, 0.f);
        int n = node0 + nd;
        if (n < NN) {
            int dg = g_deg[n];
            float dis = dg > 0 ? rsqrtf((float)dg) : 0.f;
            float4 g = ((float4*)g_gcn)[n * 16 + kg];
            float4 s = ((float4*)g_ssum)[n * 16 + kg];
            float4 u = ((float4*)g_num)[n * 16 + kg];
            mm.x = dis * g.x + 0.5f * fmaxf(u.x / (s.x + 1e-16f), 0.f);
            mm.y = dis * g.y + 0.5f * fmaxf(u.y / (s.y + 1e-16f), 0.f);
            mm.z = dis * g.z + 0.5f * fmaxf(u.z / (s.z + 1e-16f), 0.f);
            mm.w = dis * g.w + 0.5f * fmaxf(u.w / (s.w + 1e-16f), 0.f);
        }
        sMT[(kg * 4 + 0) * SA_STRIDE + nd] = mm.x;
        sMT[(kg * 4 + 1) * SA_STRIDE + nd] = mm.y;
        sMT[(kg * 4 + 2) * SA_STRIDE + nd] = mm.z;
        sMT[(kg * 4 + 3) * SA_STRIDE + nd] = mm.w;
    }

    #pragma unroll
    for (int i = 0; i < 4; i++)
        ((float4*)sW)[t + 256 * i] = ((const float4*)Wout)[t + 256 * i];
    if (t < H) sB[t] = bout[t];
    __syncthreads();

    int rg = t >> 4, cg = t & 15;
    float4 b = ((float4*)sB)[cg];
    float4 acc[4];
    #pragma unroll
    for (int j = 0; j < 4; j++) acc[j] = b;

    #pragma unroll 16
    for (int k = 0; k < H; k++) {
        float4 av = *(const float4*)&sMT[k * SA_STRIDE + rg * 4];
        float4 w  = ((const float4*)sW)[k * 16 + cg];
        acc[0].x += av.x * w.x; acc[0].y += av.x * w.y; acc[0].z += av.x * w.z; acc[0].w += av.x * w.w;
        acc[1].x += av.y * w.x; acc[1].y += av.y * w.y; acc[1].z += av.y * w.z; acc[1].w += av.y * w.w;
        acc[2].x += av.z * w.x; acc[2].y += av.z * w.y; acc[2].z += av.z * w.z; acc[2].w += av.z * w.w;
        acc[3].x += av.w * w.x; acc[3].y += av.w * w.y; acc[3].z += av.w * w.z; acc[3].w += av.w * w.w;
    }

    int nbase = node0 + rg * 4;
    #pragma unroll
    for (int j = 0; j < 4; j++) {
        int n = nbase + j;
        if (n < NN) ((float4*)out)[n * 16 + cg] = acc[j];
    }
}

extern "C" void kernel_launch(void* const* d_in, const int* in_sizes, int n_in,
                              void* d_out, int out_size) {
    const float* risk = (const float*)d_in[0];
    // d_in[1] = edge_weight (unused by the reference)
    const float* Win  = (const float*)d_in[2];
    const float* bin  = (const float*)d_in[3];
    const float* Wrel = (const float*)d_in[4];
    const float* Wout = (const float*)d_in[5];
    const float* bout = (const float*)d_in[6];
    const int*   ei   = (const int*)d_in[7];   // [2, NE]: row (dst), col (src)
    const int*   et   = (const int*)d_in[8];
    float* out = (float*)d_out;

    k_zero<<<512, 256>>>();
    k_wcomb<<<(6 * H * H + 255) / 256, 256>>>(Win, bin, Wrel);
    k_deg<<<(NE + 255) / 256, 256>>>(ei);
    k_node<<<(NN + 63) / 64, 256>>>(risk);
    k_edge<<<NE / 16, 256>>>(ei, et);
    k_out<<<(NN + 63) / 64, 256>>>(Wout, bout, out);
}